// round 14
// baseline (speedup 1.0000x reference)
#include <cuda_runtime.h>
#include <cuda_fp16.h>
#include <cstdint>
#include <math.h>

// Problem dims (fixed by the reference)
#define NB 8
#define LSEQ 4096
#define HID 512
#define KDIM 512
#define ODIM 1536              // 3*HID
#define MROWS (NB * LSEQ)      // 32768
#define CHUNK 32
#define NCHUNK (LSEQ / CHUNK)  // 128

// Scratch (allocation-free rule: __device__ globals)
__device__ __half g_preh[(size_t)MROWS * ODIM];    // 96 MB: fp16 preactivations
__device__ float g_P[NCHUNK * NB * HID];           // 2 MB: chunk prod(f)
__device__ float g_Q[NCHUNK * NB * HID];           // 2 MB: chunk affine offset
__device__ int   g_flag[NB * NCHUNK];              // partial-published flags
__device__ __half g_xhi[(size_t)MROWS * KDIM];     // 32 MB
__device__ __half g_whi[(size_t)ODIM * KDIM];      // 1.5 MB

// ---------------------------------------------------------------------------
// PTX helpers (baseline sm_80+ only — plain sm_103 target rejects tcgen05)
// ---------------------------------------------------------------------------
__device__ __forceinline__ uint32_t smem_to_u32(const void* p) {
    uint32_t a;
    asm("{ .reg .u64 t; cvta.to.shared.u64 t, %1; cvt.u32.u64 %0, t; }"
        : "=r"(a) : "l"(p));
    return a;
}

#define CP_ASYNC16(s, g) \
    asm volatile("cp.async.cg.shared.global [%0], [%1], 16;" :: "r"(s), "l"(g))
#define CP_COMMIT() asm volatile("cp.async.commit_group;" ::: "memory")
#define CP_WAIT(n)  asm volatile("cp.async.wait_group %0;" :: "n"(n) : "memory")

#define LDMX4(r0, r1, r2, r3, addr) \
    asm volatile("ldmatrix.sync.aligned.m8n8.x4.shared.b16 {%0,%1,%2,%3}, [%4];" \
                 : "=r"(r0), "=r"(r1), "=r"(r2), "=r"(r3) : "r"(addr))

#define MMA16816(d, a0, a1, a2, a3, b0, b1) \
    asm volatile("mma.sync.aligned.m16n8k16.row.col.f32.f16.f16.f32 " \
                 "{%0,%1,%2,%3}, {%4,%5,%6,%7}, {%8,%9}, {%0,%1,%2,%3};" \
                 : "+f"((d)[0]), "+f"((d)[1]), "+f"((d)[2]), "+f"((d)[3]) \
                 : "r"(a0), "r"(a1), "r"(a2), "r"(a3), "r"(b0), "r"(b1))

// ---------------------------------------------------------------------------
// Kernel 0: fp32 -> fp16 conversions (+ flag reset for the scan kernel; this
// runs first each launch, so graph replays start with clean flags)
// ---------------------------------------------------------------------------
__global__ __launch_bounds__(256)
void cvt_x_kernel(const float* __restrict__ x) {
    const size_t gtid = (size_t)blockIdx.x * 256 + threadIdx.x;
    if (gtid < NB * NCHUNK) g_flag[gtid] = 0;
    const size_t i0 = gtid * 4;
    float4 v = *(const float4*)(x + i0);
    *(__half2*)(g_xhi + i0) = __floats2half2_rn(v.x, v.y);
    *(__half2*)(g_xhi + i0 + 2) = __floats2half2_rn(v.z, v.w);
}

__global__ __launch_bounds__(256)
void cvt_w_kernel(const float* __restrict__ W) {
    const size_t i0 = ((size_t)blockIdx.x * 256 + threadIdx.x) * 4;
    float4 v = *(const float4*)(W + i0);
    *(__half2*)(g_whi + i0) = __floats2half2_rn(v.x, v.y);
    *(__half2*)(g_whi + i0 + 2) = __floats2half2_rn(v.z, v.w);
}

// ---------------------------------------------------------------------------
// Kernel 1: fp16 mma.sync GEMM, single pass, fp16 output (unchanged; it is
// at the measured legacy-HMMA pipe ceiling ~330 TF/s).
// ---------------------------------------------------------------------------
#define BK 64
#define NKC (KDIM / BK)            // 8 k-chunks
#define TILE_B (128 * BK * 2)      // 16384 bytes per tile
#define STAGE_B (2 * TILE_B)       // 32768 bytes per stage
#define NSTAGE 3
#define SM_GEMM (NSTAGE * STAGE_B) // 98304 bytes

__device__ __forceinline__ void load_stage_g(
    uint32_t sbase, int stage, int kc, int tid,
    const __half* Ah, const __half* Bh) {
    const int k0 = kc * BK;
    const uint32_t st = sbase + stage * STAGE_B;
    const __half* gsrc[2] = {Ah, Bh};
#pragma unroll
    for (int tt = 0; tt < 2; tt++) {
#pragma unroll
        for (int j = 0; j < 4; j++) {
            const int idx = j * 256 + tid;      // 0..1023
            const int row = idx >> 3;           // 0..127
            const int c = idx & 7;              // 16B chunk in 128B row
            const char* g = (const char*)(gsrc[tt] + (size_t)row * KDIM + k0 + c * 8);
            const uint32_t s = st + tt * TILE_B + row * 128 +
                               ((c ^ (row & 7)) * 16);
            CP_ASYNC16(s, g);
        }
    }
}

__global__ __launch_bounds__(256)
void gemm_mma_kernel(const float* __restrict__ bias) {
    extern __shared__ char smem[];
    const uint32_t sbase = smem_to_u32(smem);
    const int tid = threadIdx.x;
    const int lane = tid & 31;
    const int w = tid >> 5;
    const int wm = w & 3;
    const int wn = w >> 2;
    const int bx = blockIdx.x;
    const int by = blockIdx.y;

    const __half* Ah = g_xhi + (size_t)by * 128 * KDIM;
    const __half* Bh = g_whi + (size_t)bx * 128 * KDIM;

    float acc[2][8][4];
#pragma unroll
    for (int mi = 0; mi < 2; mi++)
#pragma unroll
        for (int ni = 0; ni < 8; ni++)
#pragma unroll
            for (int r = 0; r < 4; r++) acc[mi][ni][r] = 0.f;

    const int lrow = lane & 15;
    const int lhalf = lane >> 4;

    load_stage_g(sbase, 0, 0, tid, Ah, Bh); CP_COMMIT();
    load_stage_g(sbase, 1, 1, tid, Ah, Bh); CP_COMMIT();

    for (int kc = 0; kc < NKC; kc++) {
        if (kc == NKC - 1) { CP_WAIT(0); } else { CP_WAIT(1); }
        __syncthreads();
        const int stage = kc % NSTAGE;
        if (kc + 2 < NKC) {
            load_stage_g(sbase, (kc + 2) % NSTAGE, kc + 2, tid, Ah, Bh);
            CP_COMMIT();
        }

        const uint32_t st = sbase + stage * STAGE_B;
#pragma unroll
        for (int s = 0; s < 4; s++) {
            uint32_t af[2][4], bf[4][4];
#pragma unroll
            for (int mi = 0; mi < 2; mi++) {
                const int row = wm * 32 + mi * 16 + lrow;
                const int cS = (s * 2 + lhalf) ^ (row & 7);
                LDMX4(af[mi][0], af[mi][1], af[mi][2], af[mi][3],
                      st + row * 128 + cS * 16);
            }
#pragma unroll
            for (int nt = 0; nt < 4; nt++) {
                const int row = wn * 64 + nt * 16 + lrow;
                const int cS = (s * 2 + lhalf) ^ (row & 7);
                LDMX4(bf[nt][0], bf[nt][1], bf[nt][2], bf[nt][3],
                      st + TILE_B + row * 128 + cS * 16);
            }
#pragma unroll
            for (int mi = 0; mi < 2; mi++)
#pragma unroll
                for (int nt = 0; nt < 4; nt++)
#pragma unroll
                    for (int a = 0; a < 2; a++) {
                        const int ni = nt * 2 + a;
                        MMA16816(acc[mi][ni], af[mi][0], af[mi][1], af[mi][2],
                                 af[mi][3], bf[nt][a], bf[nt][a + 2]);
                    }
        }
    }

#pragma unroll
    for (int mi = 0; mi < 2; mi++) {
        const int row = by * 128 + wm * 32 + mi * 16 + (lane >> 2);
#pragma unroll
        for (int ni = 0; ni < 8; ni++) {
            const int col = bx * 128 + wn * 64 + ni * 8 + (lane & 3) * 2;
            const float b0 = bias[col], b1 = bias[col + 1];
            *(__half2*)(g_preh + (size_t)row * ODIM + col) =
                __floats2half2_rn(acc[mi][ni][0] + b0, acc[mi][ni][1] + b1);
            *(__half2*)(g_preh + (size_t)(row + 8) * ODIM + col) =
                __floats2half2_rn(acc[mi][ni][2] + b0, acc[mi][ni][3] + b1);
        }
    }
}

// ---------------------------------------------------------------------------
// Gate math (closed form):
//   f = (1+e^{-ip}) / (2 + e^{-fp} + e^{-ip});   i = 1 - f
//   g = hp>=0 ? hp+0.5 : sigmoid(hp);  v = i*g
// ---------------------------------------------------------------------------
__device__ __forceinline__ void gates(float fp, float ip, float hp,
                                      float& f, float& v) {
    const float a = __expf(-fp);
    const float b = __expf(-ip);
    f = __fdividef(1.f + b, 2.f + a + b);
    const float ig = 1.f - f;
    const float gg = (hp >= 0.f) ? (hp + 0.5f)
                                 : __fdividef(1.f, 1.f + __expf(-hp));
    v = ig * gg;
}

__device__ __forceinline__ void gates4(const __half* pre, int h4,
                                       float4& f, float4& v) {
    const __half2 fp01 = *(const __half2*)(pre + h4);
    const __half2 fp23 = *(const __half2*)(pre + h4 + 2);
    const __half2 ip01 = *(const __half2*)(pre + HID + h4);
    const __half2 ip23 = *(const __half2*)(pre + HID + h4 + 2);
    const __half2 hp01 = *(const __half2*)(pre + 2 * HID + h4);
    const __half2 hp23 = *(const __half2*)(pre + 2 * HID + h4 + 2);
    const float2 fpa = __half22float2(fp01), fpb = __half22float2(fp23);
    const float2 ipa = __half22float2(ip01), ipb = __half22float2(ip23);
    const float2 hpa = __half22float2(hp01), hpb = __half22float2(hp23);
    gates(fpa.x, ipa.x, hpa.x, f.x, v.x);
    gates(fpa.y, ipa.y, hpa.y, f.y, v.y);
    gates(fpb.x, ipb.x, hpb.x, f.z, v.z);
    gates(fpb.y, ipb.y, hpb.y, f.w, v.w);
}

// ---------------------------------------------------------------------------
// Kernel 2: FUSED single-pass chunked scan (decoupled look-back).
//   Phase A: chunk-local (P,Q) from gates; publish with fence + flag.
//   Look-back: compose predecessor partials backward to get h_start.
//   Phase B: replay chunk (pre is L2-hot from phase A) and write output.
// Grid (NCHUNK, NB): chunk on x -> predecessors have strictly smaller bid,
// so the bid-ordered CTA scheduler guarantees progress (no deadlock).
// ---------------------------------------------------------------------------
__global__ __launch_bounds__(128)
void fused_scan_kernel(float* __restrict__ out) {
    const int h4 = threadIdx.x * 4;
    const int n = blockIdx.y;
    const int c = blockIdx.x;
    const size_t m0 = (size_t)n * LSEQ + (size_t)c * CHUNK;

    // ---- Phase A: chunk-local affine (P, Q) ----
    float4 P = make_float4(1.f, 1.f, 1.f, 1.f);
    float4 Q = make_float4(0.f, 0.f, 0.f, 0.f);
#pragma unroll 4
    for (int t = 0; t < CHUNK; t++) {
        const __half* pre = g_preh + (m0 + t) * ODIM;
        float4 f, v;
        gates4(pre, h4, f, v);
        P.x *= f.x; P.y *= f.y; P.z *= f.z; P.w *= f.w;
        Q.x = fmaf(f.x, Q.x, v.x);
        Q.y = fmaf(f.y, Q.y, v.y);
        Q.z = fmaf(f.z, Q.z, v.z);
        Q.w = fmaf(f.w, Q.w, v.w);
    }
    const int base = n * HID + h4;
    *(float4*)(g_P + c * (NB * HID) + base) = P;
    *(float4*)(g_Q + c * (NB * HID) + base) = Q;
    __threadfence();
    __syncthreads();
    if (threadIdx.x == 0) atomicExch(&g_flag[n * NCHUNK + c], 1);

    // ---- Look-back: h_start = compose(chunks c-1 .. 0) applied to 1e-6 ----
    float4 hs;
    if (c == 0) {
        hs = make_float4(1e-6f, 1e-6f, 1e-6f, 1e-6f);
    } else {
        float4 Pa = make_float4(1.f, 1.f, 1.f, 1.f);
        float4 Qa = make_float4(0.f, 0.f, 0.f, 0.f);
        for (int j = c - 1; j >= 0; j--) {
            if (threadIdx.x == 0) {
                while (atomicAdd(&g_flag[n * NCHUNK + j], 0) == 0) {
                    __nanosleep(64);
                }
            }
            __syncthreads();   // all threads: flag observed by t0
            __threadfence();   // acquire before reading partials
            const float4 Pj = __ldcg((const float4*)(g_P + j * (NB * HID) + base));
            const float4 Qj = __ldcg((const float4*)(g_Q + j * (NB * HID) + base));
            Qa.x = fmaf(Pa.x, Qj.x, Qa.x);
            Qa.y = fmaf(Pa.y, Qj.y, Qa.y);
            Qa.z = fmaf(Pa.z, Qj.z, Qa.z);
            Qa.w = fmaf(Pa.w, Qj.w, Qa.w);
            Pa.x *= Pj.x; Pa.y *= Pj.y; Pa.z *= Pj.z; Pa.w *= Pj.w;
        }
        hs.x = fmaf(Pa.x, 1e-6f, Qa.x);
        hs.y = fmaf(Pa.y, 1e-6f, Qa.y);
        hs.z = fmaf(Pa.z, 1e-6f, Qa.z);
        hs.w = fmaf(Pa.w, 1e-6f, Qa.w);
    }

    // ---- Phase B: replay chunk (pre L2-hot), write output ----
    float4 hc = hs;
#pragma unroll 4
    for (int t = 0; t < CHUNK; t++) {
        const __half* pre = g_preh + (m0 + t) * ODIM;
        float4 f, v;
        gates4(pre, h4, f, v);
        hc.x = fmaf(f.x, hc.x, v.x);
        hc.y = fmaf(f.y, hc.y, v.y);
        hc.z = fmaf(f.z, hc.z, v.z);
        hc.w = fmaf(f.w, hc.w, v.w);
        *(float4*)(out + (m0 + t) * HID + h4) = hc;
    }
}

// ---------------------------------------------------------------------------
extern "C" void kernel_launch(void* const* d_in, const int* in_sizes, int n_in,
                              void* d_out, int out_size) {
    const float* x = (const float*)d_in[0];  // (8, 4096, 512)
    const float* W = (const float*)d_in[1];  // (1536, 512)
    const float* b = (const float*)d_in[2];  // (1536,)
    float* out = (float*)d_out;              // (8, 4096, 512)

    cudaFuncSetAttribute(gemm_mma_kernel,
                         cudaFuncAttributeMaxDynamicSharedMemorySize, SM_GEMM);

    cvt_x_kernel<<<(MROWS * KDIM) / (256 * 4), 256>>>(x);
    cvt_w_kernel<<<(ODIM * KDIM) / (256 * 4), 256>>>(W);

    dim3 gg(ODIM / 128, MROWS / 128);        // (12, 256)
    gemm_mma_kernel<<<gg, 256, SM_GEMM>>>(b);

    dim3 gs(NCHUNK, NB);                     // (128, 8) = 1024 blocks
    fused_scan_kernel<<<gs, 128>>>(out);
}

// round 16
// speedup vs baseline: 1.4365x; 1.4365x over previous
#include <cuda_runtime.h>
#include <cuda_fp16.h>
#include <cstdint>
#include <math.h>

// Problem dims (fixed by the reference)
#define NB 8
#define LSEQ 4096
#define HID 512
#define KDIM 512
#define ODIM 1536              // 3*HID
#define MROWS (NB * LSEQ)      // 32768
#define CHUNK 32
#define NCHUNK (LSEQ / CHUNK)  // 128

// Scratch (allocation-free rule: __device__ globals)
__device__ __half g_preh[(size_t)MROWS * ODIM];    // 96 MB: fp16 preactivations
__device__ float g_P[NCHUNK * NB * HID];           // 2 MB: chunk prod(f) (partial)
__device__ float g_Q[NCHUNK * NB * HID];           // 2 MB: chunk offset (partial)
__device__ float g_H[NCHUNK * NB * HID];           // 2 MB: inclusive chunk-end h
__device__ int   g_flag[NB * NCHUNK];              // 0=none, 1=partial, 2=inclusive
__device__ __half g_xhi[(size_t)MROWS * KDIM];     // 32 MB
__device__ __half g_whi[(size_t)ODIM * KDIM];      // 1.5 MB

// ---------------------------------------------------------------------------
// PTX helpers (baseline sm_80+ only — plain sm_103 target rejects tcgen05)
// ---------------------------------------------------------------------------
__device__ __forceinline__ uint32_t smem_to_u32(const void* p) {
    uint32_t a;
    asm("{ .reg .u64 t; cvta.to.shared.u64 t, %1; cvt.u32.u64 %0, t; }"
        : "=r"(a) : "l"(p));
    return a;
}

#define CP_ASYNC16(s, g) \
    asm volatile("cp.async.cg.shared.global [%0], [%1], 16;" :: "r"(s), "l"(g))
#define CP_COMMIT() asm volatile("cp.async.commit_group;" ::: "memory")
#define CP_WAIT(n)  asm volatile("cp.async.wait_group %0;" :: "n"(n) : "memory")

#define LDMX4(r0, r1, r2, r3, addr) \
    asm volatile("ldmatrix.sync.aligned.m8n8.x4.shared.b16 {%0,%1,%2,%3}, [%4];" \
                 : "=r"(r0), "=r"(r1), "=r"(r2), "=r"(r3) : "r"(addr))

#define MMA16816(d, a0, a1, a2, a3, b0, b1) \
    asm volatile("mma.sync.aligned.m16n8k16.row.col.f32.f16.f16.f32 " \
                 "{%0,%1,%2,%3}, {%4,%5,%6,%7}, {%8,%9}, {%0,%1,%2,%3};" \
                 : "+f"((d)[0]), "+f"((d)[1]), "+f"((d)[2]), "+f"((d)[3]) \
                 : "r"(a0), "r"(a1), "r"(a2), "r"(a3), "r"(b0), "r"(b1))

// ---------------------------------------------------------------------------
// Kernel 0: fp32 -> fp16 conversions (+ flag reset; runs first each launch,
// so graph replays start with clean flags)
// ---------------------------------------------------------------------------
__global__ __launch_bounds__(256)
void cvt_x_kernel(const float* __restrict__ x) {
    const size_t gtid = (size_t)blockIdx.x * 256 + threadIdx.x;
    if (gtid < NB * NCHUNK) g_flag[gtid] = 0;
    const size_t i0 = gtid * 4;
    float4 v = *(const float4*)(x + i0);
    *(__half2*)(g_xhi + i0) = __floats2half2_rn(v.x, v.y);
    *(__half2*)(g_xhi + i0 + 2) = __floats2half2_rn(v.z, v.w);
}

__global__ __launch_bounds__(256)
void cvt_w_kernel(const float* __restrict__ W) {
    const size_t i0 = ((size_t)blockIdx.x * 256 + threadIdx.x) * 4;
    float4 v = *(const float4*)(W + i0);
    *(__half2*)(g_whi + i0) = __floats2half2_rn(v.x, v.y);
    *(__half2*)(g_whi + i0 + 2) = __floats2half2_rn(v.z, v.w);
}

// ---------------------------------------------------------------------------
// Kernel 1: fp16 mma.sync GEMM, single pass, fp16 output (unchanged; it is
// at the measured legacy-HMMA pipe ceiling ~330 TF/s).
// ---------------------------------------------------------------------------
#define BK 64
#define NKC (KDIM / BK)            // 8 k-chunks
#define TILE_B (128 * BK * 2)      // 16384 bytes per tile
#define STAGE_B (2 * TILE_B)       // 32768 bytes per stage
#define NSTAGE 3
#define SM_GEMM (NSTAGE * STAGE_B) // 98304 bytes

__device__ __forceinline__ void load_stage_g(
    uint32_t sbase, int stage, int kc, int tid,
    const __half* Ah, const __half* Bh) {
    const int k0 = kc * BK;
    const uint32_t st = sbase + stage * STAGE_B;
    const __half* gsrc[2] = {Ah, Bh};
#pragma unroll
    for (int tt = 0; tt < 2; tt++) {
#pragma unroll
        for (int j = 0; j < 4; j++) {
            const int idx = j * 256 + tid;      // 0..1023
            const int row = idx >> 3;           // 0..127
            const int c = idx & 7;              // 16B chunk in 128B row
            const char* g = (const char*)(gsrc[tt] + (size_t)row * KDIM + k0 + c * 8);
            const uint32_t s = st + tt * TILE_B + row * 128 +
                               ((c ^ (row & 7)) * 16);
            CP_ASYNC16(s, g);
        }
    }
}

__global__ __launch_bounds__(256)
void gemm_mma_kernel(const float* __restrict__ bias) {
    extern __shared__ char smem[];
    const uint32_t sbase = smem_to_u32(smem);
    const int tid = threadIdx.x;
    const int lane = tid & 31;
    const int w = tid >> 5;
    const int wm = w & 3;
    const int wn = w >> 2;
    const int bx = blockIdx.x;
    const int by = blockIdx.y;

    const __half* Ah = g_xhi + (size_t)by * 128 * KDIM;
    const __half* Bh = g_whi + (size_t)bx * 128 * KDIM;

    float acc[2][8][4];
#pragma unroll
    for (int mi = 0; mi < 2; mi++)
#pragma unroll
        for (int ni = 0; ni < 8; ni++)
#pragma unroll
            for (int r = 0; r < 4; r++) acc[mi][ni][r] = 0.f;

    const int lrow = lane & 15;
    const int lhalf = lane >> 4;

    load_stage_g(sbase, 0, 0, tid, Ah, Bh); CP_COMMIT();
    load_stage_g(sbase, 1, 1, tid, Ah, Bh); CP_COMMIT();

    for (int kc = 0; kc < NKC; kc++) {
        if (kc == NKC - 1) { CP_WAIT(0); } else { CP_WAIT(1); }
        __syncthreads();
        const int stage = kc % NSTAGE;
        if (kc + 2 < NKC) {
            load_stage_g(sbase, (kc + 2) % NSTAGE, kc + 2, tid, Ah, Bh);
            CP_COMMIT();
        }

        const uint32_t st = sbase + stage * STAGE_B;
#pragma unroll
        for (int s = 0; s < 4; s++) {
            uint32_t af[2][4], bf[4][4];
#pragma unroll
            for (int mi = 0; mi < 2; mi++) {
                const int row = wm * 32 + mi * 16 + lrow;
                const int cS = (s * 2 + lhalf) ^ (row & 7);
                LDMX4(af[mi][0], af[mi][1], af[mi][2], af[mi][3],
                      st + row * 128 + cS * 16);
            }
#pragma unroll
            for (int nt = 0; nt < 4; nt++) {
                const int row = wn * 64 + nt * 16 + lrow;
                const int cS = (s * 2 + lhalf) ^ (row & 7);
                LDMX4(bf[nt][0], bf[nt][1], bf[nt][2], bf[nt][3],
                      st + TILE_B + row * 128 + cS * 16);
            }
#pragma unroll
            for (int mi = 0; mi < 2; mi++)
#pragma unroll
                for (int nt = 0; nt < 4; nt++)
#pragma unroll
                    for (int a = 0; a < 2; a++) {
                        const int ni = nt * 2 + a;
                        MMA16816(acc[mi][ni], af[mi][0], af[mi][1], af[mi][2],
                                 af[mi][3], bf[nt][a], bf[nt][a + 2]);
                    }
        }
    }

#pragma unroll
    for (int mi = 0; mi < 2; mi++) {
        const int row = by * 128 + wm * 32 + mi * 16 + (lane >> 2);
#pragma unroll
        for (int ni = 0; ni < 8; ni++) {
            const int col = bx * 128 + wn * 64 + ni * 8 + (lane & 3) * 2;
            const float b0 = bias[col], b1 = bias[col + 1];
            *(__half2*)(g_preh + (size_t)row * ODIM + col) =
                __floats2half2_rn(acc[mi][ni][0] + b0, acc[mi][ni][1] + b1);
            *(__half2*)(g_preh + (size_t)(row + 8) * ODIM + col) =
                __floats2half2_rn(acc[mi][ni][2] + b0, acc[mi][ni][3] + b1);
        }
    }
}

// ---------------------------------------------------------------------------
// Gate math (closed form):
//   f = (1+e^{-ip}) / (2 + e^{-fp} + e^{-ip});   i = 1 - f
//   g = hp>=0 ? hp+0.5 : sigmoid(hp);  v = i*g
// ---------------------------------------------------------------------------
__device__ __forceinline__ void gates(float fp, float ip, float hp,
                                      float& f, float& v) {
    const float a = __expf(-fp);
    const float b = __expf(-ip);
    f = __fdividef(1.f + b, 2.f + a + b);
    const float ig = 1.f - f;
    const float gg = (hp >= 0.f) ? (hp + 0.5f)
                                 : __fdividef(1.f, 1.f + __expf(-hp));
    v = ig * gg;
}

__device__ __forceinline__ void gates4(const __half* pre, int h4,
                                       float4& f, float4& v) {
    const __half2 fp01 = *(const __half2*)(pre + h4);
    const __half2 fp23 = *(const __half2*)(pre + h4 + 2);
    const __half2 ip01 = *(const __half2*)(pre + HID + h4);
    const __half2 ip23 = *(const __half2*)(pre + HID + h4 + 2);
    const __half2 hp01 = *(const __half2*)(pre + 2 * HID + h4);
    const __half2 hp23 = *(const __half2*)(pre + 2 * HID + h4 + 2);
    const float2 fpa = __half22float2(fp01), fpb = __half22float2(fp23);
    const float2 ipa = __half22float2(ip01), ipb = __half22float2(ip23);
    const float2 hpa = __half22float2(hp01), hpb = __half22float2(hp23);
    gates(fpa.x, ipa.x, hpa.x, f.x, v.x);
    gates(fpa.y, ipa.y, hpa.y, f.y, v.y);
    gates(fpb.x, ipb.x, hpb.x, f.z, v.z);
    gates(fpb.y, ipb.y, hpb.y, f.w, v.w);
}

// ---------------------------------------------------------------------------
// Kernel 2: FUSED single-pass chunked scan, TWO-LEVEL decoupled look-back.
//   Phase A: chunk-local (P,Q); publish partial with flag=1.
//   Look-back: walk predecessors backward, folding partials, but STOP at the
//              first flag=2 (inclusive) entry — expected depth 1-3.
//   Publish inclusive chunk-end H = P*h_start + Q with flag=2 (before phase
//   B, so successors unblock early).
//   Phase B: replay chunk (pre L2-hot) and write output.
// Grid (NCHUNK, NB): predecessors have strictly smaller bid -> no deadlock.
// ---------------------------------------------------------------------------
__global__ __launch_bounds__(128)
void fused_scan_kernel(float* __restrict__ out) {
    __shared__ int sf;
    const int h4 = threadIdx.x * 4;
    const int n = blockIdx.y;
    const int c = blockIdx.x;
    const size_t m0 = (size_t)n * LSEQ + (size_t)c * CHUNK;
    const int base = n * HID + h4;

    // ---- Phase A: chunk-local affine (P, Q) ----
    float4 P = make_float4(1.f, 1.f, 1.f, 1.f);
    float4 Q = make_float4(0.f, 0.f, 0.f, 0.f);
#pragma unroll 4
    for (int t = 0; t < CHUNK; t++) {
        const __half* pre = g_preh + (m0 + t) * ODIM;
        float4 f, v;
        gates4(pre, h4, f, v);
        P.x *= f.x; P.y *= f.y; P.z *= f.z; P.w *= f.w;
        Q.x = fmaf(f.x, Q.x, v.x);
        Q.y = fmaf(f.y, Q.y, v.y);
        Q.z = fmaf(f.z, Q.z, v.z);
        Q.w = fmaf(f.w, Q.w, v.w);
    }
    if (c > 0) {   // partial only useful to successors of non-first chunks? all publish
        *(float4*)(g_P + c * (NB * HID) + base) = P;
        *(float4*)(g_Q + c * (NB * HID) + base) = Q;
        __threadfence();
        __syncthreads();
        if (threadIdx.x == 0) atomicExch(&g_flag[n * NCHUNK + c], 1);
    }

    // ---- Look-back with inclusive short-circuit ----
    float4 hs;
    if (c == 0) {
        hs = make_float4(1e-6f, 1e-6f, 1e-6f, 1e-6f);
    } else {
        float4 Pa = make_float4(1.f, 1.f, 1.f, 1.f);
        float4 Qa = make_float4(0.f, 0.f, 0.f, 0.f);
        int j = c - 1;
        while (true) {
            if (threadIdx.x == 0) {
                int fv;
                do {
                    fv = atomicAdd(&g_flag[n * NCHUNK + j], 0);
                    if (fv == 0) __nanosleep(64);
                } while (fv == 0);
                sf = fv;
            }
            __syncthreads();
            const int fv = sf;
            __threadfence();   // acquire before reading partial/inclusive data
            if (fv == 2) {
                // inclusive chunk-end of j available: h_start(c)=Pa*H_j+Qa
                const float4 Hj = __ldcg((const float4*)(g_H + j * (NB * HID) + base));
                hs.x = fmaf(Pa.x, Hj.x, Qa.x);
                hs.y = fmaf(Pa.y, Hj.y, Qa.y);
                hs.z = fmaf(Pa.z, Hj.z, Qa.z);
                hs.w = fmaf(Pa.w, Hj.w, Qa.w);
                break;
            }
            // fold partial of j, move to j-1
            const float4 Pj = __ldcg((const float4*)(g_P + j * (NB * HID) + base));
            const float4 Qj = __ldcg((const float4*)(g_Q + j * (NB * HID) + base));
            Qa.x = fmaf(Pa.x, Qj.x, Qa.x);
            Qa.y = fmaf(Pa.y, Qj.y, Qa.y);
            Qa.z = fmaf(Pa.z, Qj.z, Qa.z);
            Qa.w = fmaf(Pa.w, Qj.w, Qa.w);
            Pa.x *= Pj.x; Pa.y *= Pj.y; Pa.z *= Pj.z; Pa.w *= Pj.w;
            if (--j < 0) {
                hs.x = fmaf(Pa.x, 1e-6f, Qa.x);
                hs.y = fmaf(Pa.y, 1e-6f, Qa.y);
                hs.z = fmaf(Pa.z, 1e-6f, Qa.z);
                hs.w = fmaf(Pa.w, 1e-6f, Qa.w);
                break;
            }
            __syncthreads();   // protect sf before next round's t0 write
        }
    }

    // ---- Publish inclusive chunk-end H = P*hs + Q, flag=2 (unblocks
    //      successors before we do phase B) ----
    {
        float4 He;
        He.x = fmaf(P.x, hs.x, Q.x);
        He.y = fmaf(P.y, hs.y, Q.y);
        He.z = fmaf(P.z, hs.z, Q.z);
        He.w = fmaf(P.w, hs.w, Q.w);
        *(float4*)(g_H + c * (NB * HID) + base) = He;
        __threadfence();
        __syncthreads();
        if (threadIdx.x == 0) atomicExch(&g_flag[n * NCHUNK + c], 2);
    }

    // ---- Phase B: replay chunk (pre L2-hot), write output ----
    float4 hc = hs;
#pragma unroll 4
    for (int t = 0; t < CHUNK; t++) {
        const __half* pre = g_preh + (m0 + t) * ODIM;
        float4 f, v;
        gates4(pre, h4, f, v);
        hc.x = fmaf(f.x, hc.x, v.x);
        hc.y = fmaf(f.y, hc.y, v.y);
        hc.z = fmaf(f.z, hc.z, v.z);
        hc.w = fmaf(f.w, hc.w, v.w);
        *(float4*)(out + (m0 + t) * HID + h4) = hc;
    }
}

// ---------------------------------------------------------------------------
extern "C" void kernel_launch(void* const* d_in, const int* in_sizes, int n_in,
                              void* d_out, int out_size) {
    const float* x = (const float*)d_in[0];  // (8, 4096, 512)
    const float* W = (const float*)d_in[1];  // (1536, 512)
    const float* b = (const float*)d_in[2];  // (1536,)
    float* out = (float*)d_out;              // (8, 4096, 512)

    cudaFuncSetAttribute(gemm_mma_kernel,
                         cudaFuncAttributeMaxDynamicSharedMemorySize, SM_GEMM);

    cvt_x_kernel<<<(MROWS * KDIM) / (256 * 4), 256>>>(x);
    cvt_w_kernel<<<(ODIM * KDIM) / (256 * 4), 256>>>(W);

    dim3 gg(ODIM / 128, MROWS / 128);        // (12, 256)
    gemm_mma_kernel<<<gg, 256, SM_GEMM>>>(b);

    dim3 gs(NCHUNK, NB);                     // (128, 8) = 1024 blocks
    fused_scan_kernel<<<gs, 128>>>(out);
}